// round 2
// baseline (speedup 1.0000x reference)
#include <cuda_runtime.h>
#include <cuda_bf16.h>
#include <cstdint>

// ===================== constants =====================

static constexpr int C = 256;                 // feature dim
static constexpr int GRID_G = 152;            // 1 CTA / SM on GB300
static constexpr int TPB_G = 512;
static constexpr int CHUNK = 64;              // rows of A per tile
static constexpr int NQE = 3 * 128 * 128;     // 49152 accum elems (3 quadrants)
static constexpr int ACC_BYTES = NQE * 4;     // 196608
static constexpr int T_BYTES = 256 * 128;     // transposed bf16 tile: 256 rows x 128B
static constexpr int DSMEM = 1024 + ACC_BYTES + T_BYTES;   // 230400 <= 232448 max

__device__ float g_partial[(size_t)GRID_G * NQE];   // per-CTA partial quadrants (~29.9 MB)
__device__ float g_sq[NQE];                         // reduced quadrants

// ===================== PTX helpers (base ISA only — valid on .target sm_103) ===========

__device__ __forceinline__ uint32_t smem_u32(const void* p) {
    uint32_t a;
    asm("{ .reg .u64 t; cvta.to.shared.u64 t, %1; cvt.u32.u64 %0, t; }" : "=r"(a) : "l"(p));
    return a;
}

__device__ __forceinline__ void ldsm_x4(uint32_t* r, uint32_t addr) {
    asm volatile("ldmatrix.sync.aligned.m8n8.x4.shared.b16 {%0,%1,%2,%3}, [%4];"
                 : "=r"(r[0]), "=r"(r[1]), "=r"(r[2]), "=r"(r[3]) : "r"(addr) : "memory");
}

__device__ __forceinline__ void mma16816(float* d, const uint32_t* a, const uint32_t* b) {
    asm volatile("mma.sync.aligned.m16n8k16.row.col.f32.bf16.bf16.f32 "
                 "{%0,%1,%2,%3}, {%4,%5,%6,%7}, {%8,%9}, {%0,%1,%2,%3};"
                 : "+f"(d[0]), "+f"(d[1]), "+f"(d[2]), "+f"(d[3])
                 : "r"(a[0]), "r"(a[1]), "r"(a[2]), "r"(a[3]), "r"(b[0]), "r"(b[1]));
}

__device__ __forceinline__ void lds_f32x2(float* d, uint32_t addr) {
    asm volatile("ld.shared.v2.f32 {%0,%1}, [%2];" : "=f"(d[0]), "=f"(d[1]) : "r"(addr) : "memory");
}
__device__ __forceinline__ void sts_f32x2(uint32_t addr, const float* d) {
    asm volatile("st.shared.v2.f32 [%0], {%1,%2};" :: "r"(addr), "f"(d[0]), "f"(d[1]) : "memory");
}
__device__ __forceinline__ void sts_b16(uint32_t addr, uint16_t v) {
    asm volatile("st.shared.b16 [%0], %1;" :: "r"(addr), "h"(v) : "memory");
}
__device__ __forceinline__ float lds_f32(uint32_t addr) {
    float v;
    asm volatile("ld.shared.f32 %0, [%1];" : "=f"(v) : "r"(addr) : "memory");
    return v;
}
__device__ __forceinline__ void sts_zero16(uint32_t addr) {
    asm volatile("st.shared.v4.b32 [%0], {%1,%1,%1,%1};" :: "r"(addr), "r"(0) : "memory");
}

// T tile SW128 swizzle: row (c) has 128B; addr = row*128 + (colbyte ^ ((row&7)<<4))
__device__ __forceinline__ uint32_t t_addr(uint32_t Tb, int row, int colbyte) {
    return Tb + (uint32_t)row * 128u + ((uint32_t)colbyte ^ (uint32_t)((row & 7) << 4));
}
// accumulator SMEM: [quad][i][j] fp32, row stride 512B, 32B-granular XOR swizzle on j
__device__ __forceinline__ uint32_t acc_addr(uint32_t Ab, int q, int i, int j) {
    return Ab + (uint32_t)q * 65536u + (uint32_t)i * 512u +
           (((uint32_t)j << 2) ^ (uint32_t)((i & 7) << 5));
}

// ===================== kernel 1: fused A^T A (mma.sync) + E = A copy =====================

__global__ void __launch_bounds__(TPB_G, 1)
k_gemm_copy(const float* __restrict__ A, float* __restrict__ E, int Mrows) {
    extern __shared__ char dsm[];
    const uint32_t s0 = smem_u32(dsm);
    const uint32_t Ab = (s0 + 1023u) & ~1023u;   // accum base (1024-aligned)
    const uint32_t Tb = Ab + (uint32_t)ACC_BYTES;

    const int tid = threadIdx.x;
    const int wid = tid >> 5;
    const int lane = tid & 31;

    // zero SMEM accumulators
    for (uint32_t off = (uint32_t)tid * 16u; off < (uint32_t)ACC_BYTES; off += TPB_G * 16u)
        sts_zero16(Ab + off);

    const int nchunks = Mrows / CHUNK;          // 4096
    const int bid = blockIdx.x, stride = gridDim.x;
    const int nch = (nchunks - bid + stride - 1) / stride;

    // streaming role: thread loads row m, cols [cg*32, cg*32+32)
    const int m = tid & 63;
    const int cg = tid >> 6;
    float v[32];

    auto ldg_chunk = [&](int g) {
        const float4* __restrict__ p =
            reinterpret_cast<const float4*>(A + ((size_t)(g * CHUNK + m)) * C + cg * 32);
#pragma unroll
        for (int i = 0; i < 8; i++) {
            float4 f = p[i];
            v[i * 4 + 0] = f.x; v[i * 4 + 1] = f.y; v[i * 4 + 2] = f.z; v[i * 4 + 3] = f.w;
        }
    };
    auto stg_E = [&](int g) {
        float4* __restrict__ q =
            reinterpret_cast<float4*>(E + ((size_t)(g * CHUNK + m)) * C + cg * 32);
#pragma unroll
        for (int i = 0; i < 8; i++) {
            float4 f;
            f.x = v[i * 4 + 0]; f.y = v[i * 4 + 1]; f.z = v[i * 4 + 2]; f.w = v[i * 4 + 3];
            q[i] = f;
        }
    };
    // transposed bf16 store: T[c][k], c = feature, k = row-in-chunk
    auto store_T = [&]() {
#pragma unroll
        for (int j = 0; j < 32; j++) {
            const int c = cg * 32 + j;
            __nv_bfloat16 h = __float2bfloat16_rn(v[j]);
            uint16_t hb; memcpy(&hb, &h, 2);
            sts_b16(t_addr(Tb, c, m * 2), hb);
        }
    };

    // ---- mma-phase per-lane constants ----
    // warp slab: quadrant loop qq; rows i0..i0+16 of quad, cols j0..j0+64
    const int i0 = (wid >> 1) * 16;
    const int j0 = (wid & 1) * 64;
    // ldmatrix A x4 lane roles
    const int a_im = lane >> 3, a_r = lane & 7;
    const int a_rowoff = (a_im & 1) * 8 + a_r;   // within 16-row slab
    const int a_k8 = (a_im >> 1) * 8;            // 0 or 8
    // ldmatrix B x4 lane roles (two n-tiles per load)
    const int b_im = lane >> 3, b_r = lane & 7;
    const int b_rowoff = (b_im >> 1) * 8 + b_r;  // within 16 rows (nt pair)
    const int b_k8 = (b_im & 1) * 8;
    // accum RMW lane roles
    const int cr = lane >> 2, ctg = lane & 3;

    auto mma_phase = [&]() {
        const int QA[3] = { 0, 0, 1 };
        const int QB[3] = { 0, 1, 1 };
#pragma unroll
        for (int qq = 0; qq < 3; qq++) {
            const int arow = QA[qq] * 128 + i0 + a_rowoff;
            const int bbase = QB[qq] * 128 + j0 + b_rowoff;

            float acc[32];
#pragma unroll
            for (int nt = 0; nt < 8; nt++) {
                const int j = j0 + nt * 8 + ctg * 2;
                lds_f32x2(&acc[nt * 4 + 0], acc_addr(Ab, qq, i0 + cr, j));
                lds_f32x2(&acc[nt * 4 + 2], acc_addr(Ab, qq, i0 + cr + 8, j));
            }
#pragma unroll
            for (int ks = 0; ks < 4; ks++) {
                const int k0 = ks * 16;
                uint32_t a[4];
                ldsm_x4(a, t_addr(Tb, arow, (k0 + a_k8) * 2));
#pragma unroll
                for (int np = 0; np < 4; np++) {
                    uint32_t b4[4];
                    ldsm_x4(b4, t_addr(Tb, bbase + np * 16, (k0 + b_k8) * 2));
                    mma16816(&acc[np * 8 + 0], a, &b4[0]);
                    mma16816(&acc[np * 8 + 4], a, &b4[2]);
                }
            }
#pragma unroll
            for (int nt = 0; nt < 8; nt++) {
                const int j = j0 + nt * 8 + ctg * 2;
                sts_f32x2(acc_addr(Ab, qq, i0 + cr, j), &acc[nt * 4 + 0]);
                sts_f32x2(acc_addr(Ab, qq, i0 + cr + 8, j), &acc[nt * 4 + 2]);
            }
        }
    };

    // ---- main stream loop ----
    int g = bid;
    ldg_chunk(g);
    stg_E(g);
    for (int it = 0; it < nch; ++it) {
        store_T();
        __syncthreads();                    // T visible to all warps
        const bool more = (it + 1 < nch);
        if (more) ldg_chunk(g + stride);    // overlap next LDG with mma phase
        mma_phase();
        if (more) stg_E(g + stride);
        g += stride;
        __syncthreads();                    // everyone done reading T before next store
    }

    // ---- flush accumulators to per-CTA global partials ----
    float* __restrict__ dst = g_partial + (size_t)bid * NQE;
#pragma unroll
    for (int t = 0; t < NQE / TPB_G; ++t) {
        const int idx = tid + t * TPB_G;
        const int qq = idx >> 14;
        const int rem = idx & 16383;
        const int i = rem >> 7;
        const int j = rem & 127;
        dst[idx] = lds_f32(acc_addr(Ab, qq, i, j));
    }
}

// ===================== kernel 2: reduce partials over CTAs =====================

__global__ void k_reduce() {
    const int idx = blockIdx.x * blockDim.x + threadIdx.x;   // < 49152
    float s = 0.0f;
#pragma unroll 4
    for (int c = 0; c < GRID_G; ++c)
        s += g_partial[(size_t)c * NQE + idx];
    g_sq[idx] = s;
}

// ===================== kernel 3: row softmax -> CAG =====================

__global__ void k_softmax(float* __restrict__ cag) {
    const int c = blockIdx.x;       // row
    const int d = threadIdx.x;      // col
    const int wid = d >> 5, lane = d & 31;

    // quadrant layout: g_sq[q*16384 + i*128 + j]
    float v;
    if (c < 128) {
        v = (d < 128) ? g_sq[c * 128 + d]
                      : g_sq[16384 + c * 128 + (d - 128)];
    } else {
        v = (d < 128) ? g_sq[16384 + d * 128 + (c - 128)]    // symmetry
                      : g_sq[32768 + (c - 128) * 128 + (d - 128)];
    }

    __shared__ float red[8];
    float x = v;
#pragma unroll
    for (int o = 16; o > 0; o >>= 1) x = fmaxf(x, __shfl_xor_sync(0xFFFFFFFFu, x, o));
    if (lane == 0) red[wid] = x;
    __syncthreads();
    float mx = red[0];
#pragma unroll
    for (int i = 1; i < 8; i++) mx = fmaxf(mx, red[i]);
    __syncthreads();

    const float e = expf(v - mx);
    float s = e;
#pragma unroll
    for (int o = 16; o > 0; o >>= 1) s += __shfl_xor_sync(0xFFFFFFFFu, s, o);
    if (lane == 0) red[wid] = s;
    __syncthreads();
    float sum = red[0];
#pragma unroll
    for (int i = 1; i < 8; i++) sum += red[i];

    cag[c * 256 + d] = e / sum;
}

// ===================== kernel 4: beta != 0 fallback (early-exits for beta==0) ===========

__global__ void k_beta_fallback(const float* __restrict__ A,
                                const float* __restrict__ beta,
                                float* __restrict__ out, int Mrows) {
    const float b = beta[0];
    if (b == 0.0f) return;   // E = A already written; beta * temp == 0 exactly

    const float* __restrict__ cag = out + (size_t)Mrows * C;
    const size_t total = (size_t)Mrows * C;
    const size_t gstride = (size_t)gridDim.x * blockDim.x;
    for (size_t i = (size_t)blockIdx.x * blockDim.x + threadIdx.x; i < total; i += gstride) {
        const int mm = (int)(i >> 8);
        const int cc = (int)(i & 255);
        const float* a = A + (size_t)mm * C;
        const float* gg = cag + (size_t)cc * C;
        float t = 0.0f;
        for (int dd = 0; dd < C; ++dd) t += a[dd] * gg[dd];
        out[i] = a[cc] + b * t;
    }
}

// ===================== launch =====================

extern "C" void kernel_launch(void* const* d_in, const int* in_sizes, int n_in,
                              void* d_out, int out_size) {
    const float* A    = (const float*)d_in[0];
    const float* beta = (const float*)d_in[1];
    float* out        = (float*)d_out;

    const int Mrows = in_sizes[0] / C;          // 262144
    float* E   = out;
    float* cag = out + (size_t)Mrows * C;

    static bool attr_set = false;
    if (!attr_set) {
        cudaFuncSetAttribute(k_gemm_copy, cudaFuncAttributeMaxDynamicSharedMemorySize, DSMEM);
        attr_set = true;
    }

    k_gemm_copy<<<GRID_G, TPB_G, DSMEM>>>(A, E, Mrows);
    k_reduce<<<NQE / 256, 256>>>();
    k_softmax<<<256, 256>>>(cag);
    k_beta_fallback<<<1184, 256>>>(A, beta, out, Mrows);
}

// round 3
// speedup vs baseline: 2.7250x; 2.7250x over previous
#include <cuda_runtime.h>
#include <cuda_bf16.h>
#include <cstdint>

// ===================== constants =====================

static constexpr int C = 256;               // feature dim
static constexpr int GRID_G = 152;          // 1 CTA / SM
static constexpr int TPB_G = 512;
static constexpr int CHUNK = 64;            // rows of A per pass
static constexpr int NQE = 3 * 128 * 128;   // 49152 interaction elems (3 quadrants)

static constexpr int T_STRIDE = 528;        // bf16 tile row stride (512 data + 16 pad)
static constexpr int T_BYTES = CHUNK * T_STRIDE;       // 33792
static constexpr int STAGE_BYTES = CHUNK * C * 4;      // 65536 (fp32 staging)
static constexpr int DSMEM = 1024 + STAGE_BYTES + 2 * T_BYTES;  // 134144

__device__ float g_partial[(size_t)GRID_G * NQE];   // per-CTA partials (~29.9 MB)
__device__ float g_sq[NQE];

// ===================== PTX helpers (base ISA, valid on .target sm_103) ===========

__device__ __forceinline__ uint32_t smem_u32(const void* p) {
    uint32_t a;
    asm("{ .reg .u64 t; cvta.to.shared.u64 t, %1; cvt.u32.u64 %0, t; }" : "=r"(a) : "l"(p));
    return a;
}

__device__ __forceinline__ void ldsm_x4_trans(uint32_t* r, uint32_t addr) {
    asm volatile("ldmatrix.sync.aligned.m8n8.x4.trans.shared.b16 {%0,%1,%2,%3}, [%4];"
                 : "=r"(r[0]), "=r"(r[1]), "=r"(r[2]), "=r"(r[3]) : "r"(addr) : "memory");
}

__device__ __forceinline__ void mma16816(float* d, const uint32_t* a, const uint32_t* b) {
    asm volatile("mma.sync.aligned.m16n8k16.row.col.f32.bf16.bf16.f32 "
                 "{%0,%1,%2,%3}, {%4,%5,%6,%7}, {%8,%9}, {%0,%1,%2,%3};"
                 : "+f"(d[0]), "+f"(d[1]), "+f"(d[2]), "+f"(d[3])
                 : "r"(a[0]), "r"(a[1]), "r"(a[2]), "r"(a[3]), "r"(b[0]), "r"(b[1]));
}

__device__ __forceinline__ void cp_async16(uint32_t saddr, const void* gaddr) {
    asm volatile("cp.async.cg.shared.global [%0], [%1], 16;" :: "r"(saddr), "l"(gaddr) : "memory");
}
__device__ __forceinline__ void cp_commit() {
    asm volatile("cp.async.commit_group;" ::: "memory");
}
__device__ __forceinline__ void cp_wait0() {
    asm volatile("cp.async.wait_group 0;" ::: "memory");
}

__device__ __forceinline__ void lds_f32x4(float4& f, uint32_t addr) {
    asm volatile("ld.shared.v4.f32 {%0,%1,%2,%3}, [%4];"
                 : "=f"(f.x), "=f"(f.y), "=f"(f.z), "=f"(f.w) : "r"(addr) : "memory");
}
__device__ __forceinline__ void sts_b32x2(uint32_t addr, uint32_t a, uint32_t b) {
    asm volatile("st.shared.v2.b32 [%0], {%1,%2};" :: "r"(addr), "r"(a), "r"(b) : "memory");
}

// ===================== kernel 1: fused A^T A (mma.sync, reg acc) + E = A copy ==========

__global__ void __launch_bounds__(TPB_G, 1)
k_gemm_copy(const float* __restrict__ A, float* __restrict__ E, int Mrows) {
    extern __shared__ char dsm[];
    const uint32_t s0 = smem_u32(dsm);
    const uint32_t Sb = (s0 + 1023u) & ~1023u;                 // fp32 stage base
    const uint32_t Tb0 = Sb + (uint32_t)STAGE_BYTES;           // bf16 tile buf 0
    const uint32_t Tb1 = Tb0 + (uint32_t)T_BYTES;              // bf16 tile buf 1

    const int tid = threadIdx.x;
    const int wid = tid >> 5;
    const int lane = tid & 31;

    const int nchunks = Mrows / CHUNK;                         // 4096
    const int bid = blockIdx.x, stride = gridDim.x;
    const int nch = (nchunks - bid + stride - 1) / stride;

    // streaming role: coalesced — lane-consecutive 16B units of a row
    const int rsub = tid >> 6;            // 0..7: row subgroup
    const int ucol = tid & 63;            // 16B unit within row (64 units = 256 floats)

    // register accumulators: 3 quadrants x 32 floats (m16 x n64 warp tile)
    float acc[3][32];
#pragma unroll
    for (int q = 0; q < 3; q++)
#pragma unroll
        for (int r = 0; r < 32; r++) acc[q][r] = 0.0f;

    // mma lane roles
    const int i0 = (wid >> 1) * 16;       // quadrant row slab
    const int j0 = (wid & 1) * 64;        // quadrant col slab
    const int sel = lane >> 3, l7 = lane & 7;
    const int a_krow = l7 + ((sel >> 1) << 3);   // + k0
    const int a_cofs = (sel & 1) << 3;           // + iBase
    const int b_krow = l7 + ((sel & 1) << 3);    // + k0
    const int b_cofs = (sel >> 1) << 3;          // + nBase
    const int cr = lane >> 2, ctg = lane & 3;    // D fragment roles

    auto produce = [&](int g) {          // cp.async chunk g -> stage
        const float* __restrict__ src = A + ((size_t)g * CHUNK) * C;
#pragma unroll
        for (int k = 0; k < 8; k++) {
            const int row = k * 8 + rsub;
            cp_async16(Sb + (uint32_t)(row * 1024 + ucol * 16),
                       src + (size_t)row * C + ucol * 4);
        }
        cp_commit();
    };

    auto consume = [&](int g, uint32_t Tb) {   // stage -> E (fp32) + T (bf16)
        float* __restrict__ dst = E + ((size_t)g * CHUNK) * C;
#pragma unroll
        for (int k = 0; k < 8; k++) {
            const int row = k * 8 + rsub;
            float4 f;
            lds_f32x4(f, Sb + (uint32_t)(row * 1024 + ucol * 16));
            reinterpret_cast<float4*>(dst + (size_t)row * C)[ucol] = f;
            __nv_bfloat162 h0 = __floats2bfloat162_rn(f.x, f.y);
            __nv_bfloat162 h1 = __floats2bfloat162_rn(f.z, f.w);
            uint32_t p0, p1;
            memcpy(&p0, &h0, 4); memcpy(&p1, &h1, 4);
            sts_b32x2(Tb + (uint32_t)(row * T_STRIDE + ucol * 8), p0, p1);
        }
    };

    auto mma_phase = [&](uint32_t Tb) {
        const int QA[3] = { 0, 0, 1 };
        const int QB[3] = { 0, 1, 1 };
#pragma unroll
        for (int qq = 0; qq < 3; qq++) {
            const int iBase = QA[qq] * 128 + i0;
            const int nB0   = QB[qq] * 128 + j0;
#pragma unroll
            for (int ks = 0; ks < 4; ks++) {
                const int k0 = ks * 16;
                uint32_t a[4];
                ldsm_x4_trans(a, Tb + (uint32_t)((k0 + a_krow) * T_STRIDE
                                                 + (iBase + a_cofs) * 2));
#pragma unroll
                for (int np = 0; np < 4; np++) {
                    uint32_t b4[4];
                    ldsm_x4_trans(b4, Tb + (uint32_t)((k0 + b_krow) * T_STRIDE
                                                      + (nB0 + np * 16 + b_cofs) * 2));
                    mma16816(&acc[qq][np * 8 + 0], a, &b4[0]);
                    mma16816(&acc[qq][np * 8 + 4], a, &b4[2]);
                }
            }
        }
    };

    // ---- pipeline ----
    int g = bid;
    produce(g);
    cp_wait0();
    consume(g, Tb0);
    __syncthreads();

    for (int it = 0; it < nch; ++it) {
        const uint32_t Tb = (it & 1) ? Tb1 : Tb0;
        const bool more = (it + 1 < nch);
        if (more) produce(g + stride);             // overlaps mma below
        mma_phase(Tb);
        if (more) {
            cp_wait0();
            consume(g + stride, (it & 1) ? Tb0 : Tb1);
        }
        __syncthreads();
        g += stride;
    }

    // ---- flush register accumulators -> per-CTA partials [q][i][j] ----
    float* __restrict__ dst = g_partial + (size_t)bid * NQE;
#pragma unroll
    for (int qq = 0; qq < 3; qq++) {
        float* qb = dst + qq * 16384;
#pragma unroll
        for (int np = 0; np < 4; np++) {
#pragma unroll
            for (int h = 0; h < 2; h++) {
                const int col = j0 + np * 16 + h * 8 + ctg * 2;
                const float* a4 = &acc[qq][np * 8 + h * 4];
                *reinterpret_cast<float2*>(qb + (i0 + cr) * 128 + col) =
                    make_float2(a4[0], a4[1]);
                *reinterpret_cast<float2*>(qb + (i0 + cr + 8) * 128 + col) =
                    make_float2(a4[2], a4[3]);
            }
        }
    }
}

// ===================== kernel 2: reduce partials over CTAs =====================

__global__ void k_reduce() {
    const int idx = blockIdx.x * blockDim.x + threadIdx.x;   // < 49152
    float s = 0.0f;
#pragma unroll 4
    for (int c = 0; c < GRID_G; ++c)
        s += g_partial[(size_t)c * NQE + idx];
    g_sq[idx] = s;
}

// ===================== kernel 3: row softmax -> CAG =====================

__global__ void k_softmax(float* __restrict__ cag) {
    const int c = blockIdx.x;       // row
    const int d = threadIdx.x;      // col
    const int wid = d >> 5, lane = d & 31;

    float v;
    if (c < 128) {
        v = (d < 128) ? g_sq[c * 128 + d]
                      : g_sq[16384 + c * 128 + (d - 128)];
    } else {
        v = (d < 128) ? g_sq[16384 + d * 128 + (c - 128)]    // symmetry
                      : g_sq[32768 + (c - 128) * 128 + (d - 128)];
    }

    __shared__ float red[8];
    float x = v;
#pragma unroll
    for (int o = 16; o > 0; o >>= 1) x = fmaxf(x, __shfl_xor_sync(0xFFFFFFFFu, x, o));
    if (lane == 0) red[wid] = x;
    __syncthreads();
    float mx = red[0];
#pragma unroll
    for (int i = 1; i < 8; i++) mx = fmaxf(mx, red[i]);
    __syncthreads();

    const float e = expf(v - mx);
    float s = e;
#pragma unroll
    for (int o = 16; o > 0; o >>= 1) s += __shfl_xor_sync(0xFFFFFFFFu, s, o);
    if (lane == 0) red[wid] = s;
    __syncthreads();
    float sum = red[0];
#pragma unroll
    for (int i = 1; i < 8; i++) sum += red[i];

    cag[c * 256 + d] = e / sum;
}

// ===================== kernel 4: beta != 0 fallback (early-exits for beta==0) ===========

__global__ void k_beta_fallback(const float* __restrict__ A,
                                const float* __restrict__ beta,
                                float* __restrict__ out, int Mrows) {
    const float b = beta[0];
    if (b == 0.0f) return;   // E = A already written; beta * temp == 0 exactly

    const float* __restrict__ cag = out + (size_t)Mrows * C;
    const size_t total = (size_t)Mrows * C;
    const size_t gstride = (size_t)gridDim.x * blockDim.x;
    for (size_t i = (size_t)blockIdx.x * blockDim.x + threadIdx.x; i < total; i += gstride) {
        const int mm = (int)(i >> 8);
        const int cc = (int)(i & 255);
        const float* a = A + (size_t)mm * C;
        const float* gg = cag + (size_t)cc * C;
        float t = 0.0f;
        for (int dd = 0; dd < C; ++dd) t += a[dd] * gg[dd];
        out[i] = a[cc] + b * t;
    }
}

// ===================== launch =====================

extern "C" void kernel_launch(void* const* d_in, const int* in_sizes, int n_in,
                              void* d_out, int out_size) {
    const float* A    = (const float*)d_in[0];
    const float* beta = (const float*)d_in[1];
    float* out        = (float*)d_out;

    const int Mrows = in_sizes[0] / C;          // 262144
    float* E   = out;
    float* cag = out + (size_t)Mrows * C;

    static bool attr_set = false;
    if (!attr_set) {
        cudaFuncSetAttribute(k_gemm_copy, cudaFuncAttributeMaxDynamicSharedMemorySize, DSMEM);
        attr_set = true;
    }

    k_gemm_copy<<<GRID_G, TPB_G, DSMEM>>>(A, E, Mrows);
    k_reduce<<<NQE / 256, 256>>>();
    k_softmax<<<256, 256>>>(cag);
    k_beta_fallback<<<1184, 256>>>(A, beta, out, Mrows);
}

// round 4
// speedup vs baseline: 2.7544x; 1.0108x over previous
#include <cuda_runtime.h>
#include <cuda_bf16.h>
#include <cstdint>

// ===================== constants =====================

static constexpr int C = 256;               // feature dim
static constexpr int GRID_G = 152;          // 1 CTA / SM
static constexpr int TPB_G = 512;
static constexpr int CHUNK = 64;            // rows of A per pass
static constexpr int NQE = 3 * 128 * 128;   // 49152 interaction elems (3 quadrants)

static constexpr int T_STRIDE = 528;        // bf16 tile row stride (512 data + 16 pad)
static constexpr int T_BYTES = CHUNK * T_STRIDE;       // 33792
static constexpr int STAGE_BYTES = CHUNK * C * 4;      // 65536 (fp32 staging)
static constexpr int DSMEM = 1024 + STAGE_BYTES + 2 * T_BYTES;  // 134144

__device__ float g_partial[(size_t)GRID_G * NQE];   // per-CTA partials (~29.9 MB)
__device__ float g_sq[NQE];

// ===================== PTX helpers (base ISA, valid on .target sm_103) ===========

__device__ __forceinline__ uint32_t smem_u32(const void* p) {
    uint32_t a;
    asm("{ .reg .u64 t; cvta.to.shared.u64 t, %1; cvt.u32.u64 %0, t; }" : "=r"(a) : "l"(p));
    return a;
}

__device__ __forceinline__ void ldsm_x4_trans(uint32_t* r, uint32_t addr) {
    asm volatile("ldmatrix.sync.aligned.m8n8.x4.trans.shared.b16 {%0,%1,%2,%3}, [%4];"
                 : "=r"(r[0]), "=r"(r[1]), "=r"(r[2]), "=r"(r[3]) : "r"(addr) : "memory");
}

__device__ __forceinline__ void mma16816(float* d, const uint32_t* a, const uint32_t* b) {
    asm volatile("mma.sync.aligned.m16n8k16.row.col.f32.bf16.bf16.f32 "
                 "{%0,%1,%2,%3}, {%4,%5,%6,%7}, {%8,%9}, {%0,%1,%2,%3};"
                 : "+f"(d[0]), "+f"(d[1]), "+f"(d[2]), "+f"(d[3])
                 : "r"(a[0]), "r"(a[1]), "r"(a[2]), "r"(a[3]), "r"(b[0]), "r"(b[1]));
}

__device__ __forceinline__ void cp_async16(uint32_t saddr, const void* gaddr) {
    asm volatile("cp.async.cg.shared.global [%0], [%1], 16;" :: "r"(saddr), "l"(gaddr) : "memory");
}
__device__ __forceinline__ void cp_commit() {
    asm volatile("cp.async.commit_group;" ::: "memory");
}
__device__ __forceinline__ void cp_wait0() {
    asm volatile("cp.async.wait_group 0;" ::: "memory");
}

__device__ __forceinline__ void lds_f32x4(float4& f, uint32_t addr) {
    asm volatile("ld.shared.v4.f32 {%0,%1,%2,%3}, [%4];"
                 : "=f"(f.x), "=f"(f.y), "=f"(f.z), "=f"(f.w) : "r"(addr) : "memory");
}
__device__ __forceinline__ void sts_b32x2(uint32_t addr, uint32_t a, uint32_t b) {
    asm volatile("st.shared.v2.b32 [%0], {%1,%2};" :: "r"(addr), "r"(a), "r"(b) : "memory");
}

// ===================== kernel 1: fused A^T A (mma.sync, reg acc) + E = A copy ==========

__global__ void __launch_bounds__(TPB_G, 1)
k_gemm_copy(const float* __restrict__ A, float* __restrict__ E, int Mrows) {
    extern __shared__ char dsm[];
    const uint32_t s0 = smem_u32(dsm);
    const uint32_t Sb = (s0 + 1023u) & ~1023u;                 // fp32 stage base
    const uint32_t Tb0 = Sb + (uint32_t)STAGE_BYTES;           // bf16 tile buf 0
    const uint32_t Tb1 = Tb0 + (uint32_t)T_BYTES;              // bf16 tile buf 1

    const int tid = threadIdx.x;
    const int wid = tid >> 5;
    const int lane = tid & 31;

    const int nchunks = Mrows / CHUNK;                         // 4096
    const int bid = blockIdx.x, stride = gridDim.x;
    const int nch = (nchunks - bid + stride - 1) / stride;

    // streaming role: coalesced — lane-consecutive 16B units of a row
    const int rsub = tid >> 6;            // 0..7: row subgroup
    const int ucol = tid & 63;            // 16B unit within row (64 units = 256 floats)

    // register accumulators: 3 quadrants x 32 floats (m16 x n64 warp tile)
    float acc[3][32];
#pragma unroll
    for (int q = 0; q < 3; q++)
#pragma unroll
        for (int r = 0; r < 32; r++) acc[q][r] = 0.0f;

    // mma lane roles
    const int i0 = (wid >> 1) * 16;       // quadrant row slab
    const int j0 = (wid & 1) * 64;        // quadrant col slab
    const int sel = lane >> 3, l7 = lane & 7;
    const int a_krow = l7 + ((sel >> 1) << 3);   // + k0
    const int a_cofs = (sel & 1) << 3;           // + iBase
    const int b_krow = l7 + ((sel & 1) << 3);    // + k0
    const int b_cofs = (sel >> 1) << 3;          // + nBase
    const int cr = lane >> 2, ctg = lane & 3;    // D fragment roles

    auto produce = [&](int g) {          // cp.async chunk g -> stage
        const float* __restrict__ src = A + ((size_t)g * CHUNK) * C;
#pragma unroll
        for (int k = 0; k < 8; k++) {
            const int row = k * 8 + rsub;
            cp_async16(Sb + (uint32_t)(row * 1024 + ucol * 16),
                       src + (size_t)row * C + ucol * 4);
        }
        cp_commit();
    };

    auto consume = [&](int g, uint32_t Tb) {   // stage -> E (fp32) + T (bf16)
        float* __restrict__ dst = E + ((size_t)g * CHUNK) * C;
#pragma unroll
        for (int k = 0; k < 8; k++) {
            const int row = k * 8 + rsub;
            float4 f;
            lds_f32x4(f, Sb + (uint32_t)(row * 1024 + ucol * 16));
            reinterpret_cast<float4*>(dst + (size_t)row * C)[ucol] = f;
            __nv_bfloat162 h0 = __floats2bfloat162_rn(f.x, f.y);
            __nv_bfloat162 h1 = __floats2bfloat162_rn(f.z, f.w);
            uint32_t p0, p1;
            memcpy(&p0, &h0, 4); memcpy(&p1, &h1, 4);
            sts_b32x2(Tb + (uint32_t)(row * T_STRIDE + ucol * 8), p0, p1);
        }
    };

    auto mma_phase = [&](uint32_t Tb) {
        const int QA[3] = { 0, 0, 1 };
        const int QB[3] = { 0, 1, 1 };
#pragma unroll
        for (int qq = 0; qq < 3; qq++) {
            const int iBase = QA[qq] * 128 + i0;
            const int nB0   = QB[qq] * 128 + j0;
#pragma unroll
            for (int ks = 0; ks < 4; ks++) {
                const int k0 = ks * 16;
                uint32_t a[4];
                ldsm_x4_trans(a, Tb + (uint32_t)((k0 + a_krow) * T_STRIDE
                                                 + (iBase + a_cofs) * 2));
#pragma unroll
                for (int np = 0; np < 4; np++) {
                    uint32_t b4[4];
                    ldsm_x4_trans(b4, Tb + (uint32_t)((k0 + b_krow) * T_STRIDE
                                                      + (nB0 + np * 16 + b_cofs) * 2));
                    mma16816(&acc[qq][np * 8 + 0], a, &b4[0]);
                    mma16816(&acc[qq][np * 8 + 4], a, &b4[2]);
                }
            }
        }
    };

    // ---- pipeline ----
    int g = bid;
    produce(g);
    cp_wait0();
    consume(g, Tb0);
    __syncthreads();

    for (int it = 0; it < nch; ++it) {
        const uint32_t Tb = (it & 1) ? Tb1 : Tb0;
        const bool more = (it + 1 < nch);
        if (more) produce(g + stride);             // overlaps mma below
        mma_phase(Tb);
        if (more) {
            cp_wait0();
            consume(g + stride, (it & 1) ? Tb0 : Tb1);
        }
        __syncthreads();
        g += stride;
    }

    // ---- flush register accumulators -> per-CTA partials [q][i][j] ----
    float* __restrict__ dst = g_partial + (size_t)bid * NQE;
#pragma unroll
    for (int qq = 0; qq < 3; qq++) {
        float* qb = dst + qq * 16384;
#pragma unroll
        for (int np = 0; np < 4; np++) {
#pragma unroll
            for (int h = 0; h < 2; h++) {
                const int col = j0 + np * 16 + h * 8 + ctg * 2;
                const float* a4 = &acc[qq][np * 8 + h * 4];
                *reinterpret_cast<float2*>(qb + (i0 + cr) * 128 + col) =
                    make_float2(a4[0], a4[1]);
                *reinterpret_cast<float2*>(qb + (i0 + cr + 8) * 128 + col) =
                    make_float2(a4[2], a4[3]);
            }
        }
    }
}

// ===================== kernel 2: reduce partials over CTAs =====================

__global__ void k_reduce() {
    const int idx = blockIdx.x * blockDim.x + threadIdx.x;   // < 49152
    float s = 0.0f;
#pragma unroll 4
    for (int c = 0; c < GRID_G; ++c)
        s += g_partial[(size_t)c * NQE + idx];
    g_sq[idx] = s;
}

// ===================== kernel 3: row softmax -> CAG =====================

__global__ void k_softmax(float* __restrict__ cag) {
    const int c = blockIdx.x;       // row
    const int d = threadIdx.x;      // col
    const int wid = d >> 5, lane = d & 31;

    float v;
    if (c < 128) {
        v = (d < 128) ? g_sq[c * 128 + d]
                      : g_sq[16384 + c * 128 + (d - 128)];
    } else {
        v = (d < 128) ? g_sq[16384 + d * 128 + (c - 128)]    // symmetry
                      : g_sq[32768 + (c - 128) * 128 + (d - 128)];
    }

    __shared__ float red[8];
    float x = v;
#pragma unroll
    for (int o = 16; o > 0; o >>= 1) x = fmaxf(x, __shfl_xor_sync(0xFFFFFFFFu, x, o));
    if (lane == 0) red[wid] = x;
    __syncthreads();
    float mx = red[0];
#pragma unroll
    for (int i = 1; i < 8; i++) mx = fmaxf(mx, red[i]);
    __syncthreads();

    const float e = expf(v - mx);
    float s = e;
#pragma unroll
    for (int o = 16; o > 0; o >>= 1) s += __shfl_xor_sync(0xFFFFFFFFu, s, o);
    if (lane == 0) red[wid] = s;
    __syncthreads();
    float sum = red[0];
#pragma unroll
    for (int i = 1; i < 8; i++) sum += red[i];

    cag[c * 256 + d] = e / sum;
}

// ===================== kernel 4: beta != 0 fallback (early-exits for beta==0) ===========

__global__ void k_beta_fallback(const float* __restrict__ A,
                                const float* __restrict__ beta,
                                float* __restrict__ out, int Mrows) {
    const float b = beta[0];
    if (b == 0.0f) return;   // E = A already written; beta * temp == 0 exactly

    const float* __restrict__ cag = out + (size_t)Mrows * C;
    const size_t total = (size_t)Mrows * C;
    const size_t gstride = (size_t)gridDim.x * blockDim.x;
    for (size_t i = (size_t)blockIdx.x * blockDim.x + threadIdx.x; i < total; i += gstride) {
        const int mm = (int)(i >> 8);
        const int cc = (int)(i & 255);
        const float* a = A + (size_t)mm * C;
        const float* gg = cag + (size_t)cc * C;
        float t = 0.0f;
        for (int dd = 0; dd < C; ++dd) t += a[dd] * gg[dd];
        out[i] = a[cc] + b * t;
    }
}

// ===================== launch =====================

extern "C" void kernel_launch(void* const* d_in, const int* in_sizes, int n_in,
                              void* d_out, int out_size) {
    const float* A    = (const float*)d_in[0];
    const float* beta = (const float*)d_in[1];
    float* out        = (float*)d_out;

    const int Mrows = in_sizes[0] / C;          // 262144
    float* E   = out;
    float* cag = out + (size_t)Mrows * C;

    static bool attr_set = false;
    if (!attr_set) {
        cudaFuncSetAttribute(k_gemm_copy, cudaFuncAttributeMaxDynamicSharedMemorySize, DSMEM);
        attr_set = true;
    }

    k_gemm_copy<<<GRID_G, TPB_G, DSMEM>>>(A, E, Mrows);
    k_reduce<<<NQE / 256, 256>>>();
    k_softmax<<<256, 256>>>(cag);
    k_beta_fallback<<<1184, 256>>>(A, beta, out, Mrows);
}